// round 1
// baseline (speedup 1.0000x reference)
#include <cuda_runtime.h>

#define B_ 32
#define S_ 4096
#define H_ 1024
#define NSPANS_ 16
#define NCLS_ 25

// Scratch (no allocation allowed in kernel_launch)
__device__ float g_pooled[B_ * H_];
__device__ float g_h1[B_ * H_];

// ---------------------------------------------------------------------------
// Kernel 1: span-gather mean pooling.
// grid: (B, H_/256) ; block: 256 threads. Each block handles a 256-wide slice
// of H for one batch row. Only touches tokens inside valid spans.
// ---------------------------------------------------------------------------
__global__ void pool_kernel(const float* __restrict__ emb,
                            const int* __restrict__ spans,
                            float* __restrict__ pooled) {
    const int b = blockIdx.x;
    const int h = blockIdx.y * 256 + threadIdx.x;

    __shared__ int s_start[NSPANS_];
    __shared__ int s_end[NSPANS_];
    __shared__ int s_n;
    if (threadIdx.x == 0) {
        int n = 0;
        #pragma unroll
        for (; n < NSPANS_; n++) {
            int a = spans[b * (NSPANS_ * 2) + 2 * n];
            int e = spans[b * (NSPANS_ * 2) + 2 * n + 1];
            if (a == 0 && e == 0) break;   // torch 'break' semantics
            s_start[n] = a;
            s_end[n]   = e;
        }
        s_n = n;
    }
    __syncthreads();

    const int nv = s_n;
    const float* base = emb + (size_t)b * S_ * H_ + h;

    float a0 = 0.f, a1 = 0.f, a2 = 0.f, a3 = 0.f;
    int total = 0;
    for (int n = 0; n < nv; n++) {
        const int s = s_start[n];
        const int e = s_end[n];
        total += e - s;
        int t = s;
        // 4 independent accumulators -> MLP=4 outstanding DRAM loads
        for (; t + 3 < e; t += 4) {
            a0 += base[(size_t)(t + 0) * H_];
            a1 += base[(size_t)(t + 1) * H_];
            a2 += base[(size_t)(t + 2) * H_];
            a3 += base[(size_t)(t + 3) * H_];
        }
        for (; t < e; t++) a0 += base[(size_t)t * H_];
    }
    const float sum = (a0 + a1) + (a2 + a3);
    pooled[b * H_ + h] = sum / (float)total;
}

// ---------------------------------------------------------------------------
// Kernel 2: h1 = relu(pooled @ W1 + b1).   W1 is [H,H] row-major.
// grid: (H_/32 j-tiles, B_/8 b-groups) ; block: (32, 8).
// pooled rows for the 8 batches staged in smem; W1 column loads coalesced.
// ---------------------------------------------------------------------------
__global__ void fc1_kernel(const float* __restrict__ pooled,
                           const float* __restrict__ W1,
                           const float* __restrict__ b1,
                           float* __restrict__ h1) {
    const int j = blockIdx.x * 32 + threadIdx.x;
    const int brow = blockIdx.y * 8 + threadIdx.y;

    __shared__ float sp[8][H_];   // 32 KB
    const int tid = threadIdx.y * 32 + threadIdx.x;
    for (int k = tid; k < 8 * H_; k += 256) {
        sp[k >> 10][k & (H_ - 1)] =
            pooled[(blockIdx.y * 8 + (k >> 10)) * H_ + (k & (H_ - 1))];
    }
    __syncthreads();

    float acc = b1[j];
    const float* w = W1 + j;
    const float* p = sp[threadIdx.y];
    #pragma unroll 8
    for (int i = 0; i < H_; i++) {
        acc += p[i] * w[(size_t)i * H_];
    }
    h1[brow * H_ + j] = fmaxf(acc, 0.f);
}

// ---------------------------------------------------------------------------
// Kernel 3: out = sigmoid(h1 @ W2 + b2).   W2 is [H, NCLS] row-major.
// grid: B ; block: 128. Strided dot, warp-shuffle reduce, smem cross-warp.
// ---------------------------------------------------------------------------
__global__ void fc2_kernel(const float* __restrict__ h1,
                           const float* __restrict__ W2,
                           const float* __restrict__ b2,
                           float* __restrict__ out) {
    const int b = blockIdx.x;
    const int tid = threadIdx.x;

    float acc[NCLS_];
    #pragma unroll
    for (int c = 0; c < NCLS_; c++) acc[c] = 0.f;

    const float* hrow = h1 + b * H_;
    for (int i = tid; i < H_; i += 128) {
        const float hv = hrow[i];
        const float* w = W2 + i * NCLS_;
        #pragma unroll
        for (int c = 0; c < NCLS_; c++) acc[c] += hv * w[c];
    }

    #pragma unroll
    for (int c = 0; c < NCLS_; c++) {
        #pragma unroll
        for (int off = 16; off > 0; off >>= 1)
            acc[c] += __shfl_down_sync(0xffffffffu, acc[c], off);
    }

    __shared__ float red[4][NCLS_];
    const int warp = tid >> 5, lane = tid & 31;
    if (lane == 0) {
        #pragma unroll
        for (int c = 0; c < NCLS_; c++) red[warp][c] = acc[c];
    }
    __syncthreads();

    if (tid < NCLS_) {
        const float v = red[0][tid] + red[1][tid] + red[2][tid] + red[3][tid]
                        + b2[tid];
        out[b * NCLS_ + tid] = 1.f / (1.f + __expf(-v));
    }
}

// ---------------------------------------------------------------------------
extern "C" void kernel_launch(void* const* d_in, const int* in_sizes, int n_in,
                              void* d_out, int out_size) {
    const float* all_emb = (const float*)d_in[0];
    const int*   spans   = (const int*)d_in[1];
    const float* W1      = (const float*)d_in[2];
    const float* b1      = (const float*)d_in[3];
    const float* W2      = (const float*)d_in[4];
    const float* b2      = (const float*)d_in[5];
    float* out = (float*)d_out;

    float* pooled;
    float* h1;
    cudaGetSymbolAddress((void**)&pooled, g_pooled);
    cudaGetSymbolAddress((void**)&h1, g_h1);

    {
        dim3 grid(B_, H_ / 256);
        pool_kernel<<<grid, 256>>>(all_emb, spans, pooled);
    }
    {
        dim3 grid(H_ / 32, B_ / 8);
        dim3 block(32, 8);
        fc1_kernel<<<grid, block>>>(pooled, W1, b1, h1);
    }
    {
        fc2_kernel<<<B_, 128>>>(h1, W2, b2, out);
    }
}

// round 2
// speedup vs baseline: 1.2555x; 1.2555x over previous
#include <cuda_runtime.h>

#define B_ 32
#define S_ 4096
#define H_ 1024
#define NSPANS_ 16
#define NCLS_ 25
#define H4_ (H_ / 4)   // 256 float4 per row

// Scratch (no allocation allowed in kernel_launch)
__device__ float g_pooled[B_ * H_];   // span-sum accumulator (zeroed each call)
__device__ float g_h1[B_ * H_];

__device__ __forceinline__ void f4add(float4& a, const float4 b) {
    a.x += b.x; a.y += b.y; a.z += b.z; a.w += b.w;
}

// ---------------------------------------------------------------------------
// Kernel 0: zero the pooled accumulator.
// ---------------------------------------------------------------------------
__global__ void zero_kernel(float* __restrict__ pooled) {
    pooled[blockIdx.x * 256 + threadIdx.x] = 0.f;
}

// ---------------------------------------------------------------------------
// Kernel 1: span gather-sum. grid (B, NSPANS), block 256 threads.
// Each block handles ONE span; thread t owns float4 column t (16B of H).
// Overlapping spans accumulate via atomicAdd (matches cat-then-mean).
// ---------------------------------------------------------------------------
__global__ void pool_kernel(const float* __restrict__ emb,
                            const int* __restrict__ spans,
                            float* __restrict__ pooled) {
    const int b = blockIdx.x;
    const int n = blockIdx.y;

    __shared__ int ss, se, svalid;
    if (threadIdx.x == 0) {
        const int* row = spans + b * (NSPANS_ * 2);
        int s = row[2 * n], e = row[2 * n + 1];
        int v = !(s == 0 && e == 0);
        // torch 'break' semantics: valid only if all earlier spans nonzero
        for (int m = 0; m < n && v; m++) {
            if (row[2 * m] == 0 && row[2 * m + 1] == 0) v = 0;
        }
        ss = s; se = e; svalid = v;
    }
    __syncthreads();
    if (!svalid) return;

    const int s = ss, e = se;
    const float4* base = (const float4*)emb + (size_t)b * S_ * H4_ + threadIdx.x;

    float4 a0 = {0,0,0,0}, a1 = {0,0,0,0}, a2 = {0,0,0,0}, a3 = {0,0,0,0};
    int t = s;
    for (; t + 3 < e; t += 4) {
        f4add(a0, base[(size_t)(t + 0) * H4_]);
        f4add(a1, base[(size_t)(t + 1) * H4_]);
        f4add(a2, base[(size_t)(t + 2) * H4_]);
        f4add(a3, base[(size_t)(t + 3) * H4_]);
    }
    for (; t < e; t++) f4add(a0, base[(size_t)t * H4_]);

    f4add(a0, a1); f4add(a2, a3); f4add(a0, a2);

    float* dst = pooled + b * H_ + threadIdx.x * 4;
    atomicAdd(dst + 0, a0.x);
    atomicAdd(dst + 1, a0.y);
    atomicAdd(dst + 2, a0.z);
    atomicAdd(dst + 3, a0.w);
}

// ---------------------------------------------------------------------------
// Kernel 2: h1 = relu((pooled_sum / count) @ W1 + b1).  W1 [H,H] row-major.
// grid: (H_/32 j-tiles, B_/8 b-groups) ; block: (32, 8).
// ---------------------------------------------------------------------------
__global__ void fc1_kernel(const float* __restrict__ pooled,
                           const int* __restrict__ spans,
                           const float* __restrict__ W1,
                           const float* __restrict__ b1,
                           float* __restrict__ h1) {
    const int j = blockIdx.x * 32 + threadIdx.x;
    const int brow = blockIdx.y * 8 + threadIdx.y;
    const int tid = threadIdx.y * 32 + threadIdx.x;

    __shared__ float sp[8][H_];   // 32 KB
    __shared__ float s_inv[8];

    if (tid < 8) {
        const int* row = spans + (blockIdx.y * 8 + tid) * (NSPANS_ * 2);
        int total = 0;
        #pragma unroll
        for (int m = 0; m < NSPANS_; m++) {
            int a = row[2 * m], e = row[2 * m + 1];
            if (a == 0 && e == 0) break;
            total += e - a;
        }
        s_inv[tid] = 1.0f / (float)total;
    }
    __syncthreads();

    // fill smem with pooled/total (float4)
    const float4* psrc = (const float4*)(pooled + blockIdx.y * 8 * H_);
    float4* pdst = (float4*)&sp[0][0];
    for (int k = tid; k < 8 * H4_; k += 256) {
        float4 v = psrc[k];
        const float inv = s_inv[k >> 8];
        v.x *= inv; v.y *= inv; v.z *= inv; v.w *= inv;
        pdst[k] = v;
    }
    __syncthreads();

    float acc = b1[j];
    const float* w = W1 + j;
    const float* p = sp[threadIdx.y];
    #pragma unroll 8
    for (int i = 0; i < H_; i++) {
        acc += p[i] * w[(size_t)i * H_];
    }
    h1[brow * H_ + j] = fmaxf(acc, 0.f);
}

// ---------------------------------------------------------------------------
// Kernel 3: out = sigmoid(h1 @ W2 + b2).  W2 [H, NCLS] row-major.
// ---------------------------------------------------------------------------
__global__ void fc2_kernel(const float* __restrict__ h1,
                           const float* __restrict__ W2,
                           const float* __restrict__ b2,
                           float* __restrict__ out) {
    const int b = blockIdx.x;
    const int tid = threadIdx.x;

    float acc[NCLS_];
    #pragma unroll
    for (int c = 0; c < NCLS_; c++) acc[c] = 0.f;

    const float* hrow = h1 + b * H_;
    for (int i = tid; i < H_; i += 128) {
        const float hv = hrow[i];
        const float* w = W2 + i * NCLS_;
        #pragma unroll
        for (int c = 0; c < NCLS_; c++) acc[c] += hv * w[c];
    }

    #pragma unroll
    for (int c = 0; c < NCLS_; c++) {
        #pragma unroll
        for (int off = 16; off > 0; off >>= 1)
            acc[c] += __shfl_down_sync(0xffffffffu, acc[c], off);
    }

    __shared__ float red[4][NCLS_];
    const int warp = tid >> 5, lane = tid & 31;
    if (lane == 0) {
        #pragma unroll
        for (int c = 0; c < NCLS_; c++) red[warp][c] = acc[c];
    }
    __syncthreads();

    if (tid < NCLS_) {
        const float v = red[0][tid] + red[1][tid] + red[2][tid] + red[3][tid]
                        + b2[tid];
        out[b * NCLS_ + tid] = 1.f / (1.f + __expf(-v));
    }
}

// ---------------------------------------------------------------------------
extern "C" void kernel_launch(void* const* d_in, const int* in_sizes, int n_in,
                              void* d_out, int out_size) {
    const float* all_emb = (const float*)d_in[0];
    const int*   spans   = (const int*)d_in[1];
    const float* W1      = (const float*)d_in[2];
    const float* b1      = (const float*)d_in[3];
    const float* W2      = (const float*)d_in[4];
    const float* b2      = (const float*)d_in[5];
    float* out = (float*)d_out;

    float* pooled;
    float* h1;
    cudaGetSymbolAddress((void**)&pooled, g_pooled);
    cudaGetSymbolAddress((void**)&h1, g_h1);

    zero_kernel<<<B_ * H_ / 256, 256>>>(pooled);
    {
        dim3 grid(B_, NSPANS_);
        pool_kernel<<<grid, 256>>>(all_emb, spans, pooled);
    }
    {
        dim3 grid(H_ / 32, B_ / 8);
        dim3 block(32, 8);
        fc1_kernel<<<grid, block>>>(pooled, spans, W1, b1, h1);
    }
    {
        fc2_kernel<<<B_, 128>>>(h1, W2, b2, out);
    }
}

// round 3
// speedup vs baseline: 1.4847x; 1.1825x over previous
#include <cuda_runtime.h>

#define B_ 32
#define S_ 4096
#define H_ 1024
#define NSPANS_ 16
#define NCLS_ 25
#define H4_ (H_ / 4)      // 256 float4 per row
#define CHUNK_ 16         // tokens per pool block
#define NCHUNK_ 4         // ceil(63 / CHUNK_)

// Scratch (no allocation allowed in kernel_launch)
__device__ float g_pooled[B_ * H_];       // span-sum accumulator
__device__ float g_logits[B_ * NCLS_];    // pre-sigmoid logits accumulator

__device__ __forceinline__ void f4add(float4& a, const float4 b) {
    a.x += b.x; a.y += b.y; a.z += b.z; a.w += b.w;
}

// ---------------------------------------------------------------------------
// Kernel 0: zero the accumulators (pooled 32K floats + logits 800 floats).
// ---------------------------------------------------------------------------
__global__ void zero_kernel(float* __restrict__ pooled,
                            float* __restrict__ logits) {
    const int idx = blockIdx.x * 256 + threadIdx.x;
    pooled[idx] = 0.f;
    if (idx < B_ * NCLS_) logits[idx] = 0.f;
}

// ---------------------------------------------------------------------------
// Kernel 1: span gather-sum. grid (B, NSPANS, NCHUNK), block 256.
// Each block: one 16-token chunk of one span; thread t owns float4 column t.
// Overlapping spans accumulate via atomicAdd (matches cat-then-mean).
// ---------------------------------------------------------------------------
__global__ void pool_kernel(const float* __restrict__ emb,
                            const int* __restrict__ spans,
                            float* __restrict__ pooled) {
    const int b = blockIdx.x;
    const int n = blockIdx.y;
    const int c = blockIdx.z;

    __shared__ int ss, se, svalid;
    if (threadIdx.x == 0) {
        const int* row = spans + b * (NSPANS_ * 2);
        int s = row[2 * n], e = row[2 * n + 1];
        int v = !(s == 0 && e == 0);
        // torch 'break' semantics: valid only if all earlier spans nonzero
        for (int m = 0; m < n && v; m++) {
            if (row[2 * m] == 0 && row[2 * m + 1] == 0) v = 0;
        }
        int cs = s + c * CHUNK_;
        int ce = cs + CHUNK_ < e ? cs + CHUNK_ : e;
        ss = cs; se = ce; svalid = v && (cs < e);
    }
    __syncthreads();
    if (!svalid) return;

    const int s = ss, e = se;
    const float4* base = (const float4*)emb + (size_t)b * S_ * H4_ + threadIdx.x;

    float4 a0 = {0,0,0,0}, a1 = {0,0,0,0}, a2 = {0,0,0,0}, a3 = {0,0,0,0};
    int t = s;
    for (; t + 3 < e; t += 4) {
        f4add(a0, base[(size_t)(t + 0) * H4_]);
        f4add(a1, base[(size_t)(t + 1) * H4_]);
        f4add(a2, base[(size_t)(t + 2) * H4_]);
        f4add(a3, base[(size_t)(t + 3) * H4_]);
    }
    for (; t < e; t++) f4add(a0, base[(size_t)t * H4_]);

    f4add(a0, a1); f4add(a2, a3); f4add(a0, a2);

    float* dst = pooled + b * H_ + threadIdx.x * 4;
    atomicAdd(dst + 0, a0.x);
    atomicAdd(dst + 1, a0.y);
    atomicAdd(dst + 2, a0.z);
    atomicAdd(dst + 3, a0.w);
}

// ---------------------------------------------------------------------------
// Kernel 2: fused fc1 + fc2-partial.
//   h[b,j] = relu((pooled[b,:]/count[b]) @ W1[:,j] + b1[j])
//   logits[b,c] += sum_j h[b,j] * W2[j,c]     (atomicAdd)
// grid: (H_/32 j-tiles, B_/8 b-groups) ; block: (32, 8). Warp = one batch row.
// ---------------------------------------------------------------------------
__global__ void fc1_kernel(const float* __restrict__ pooled,
                           const int* __restrict__ spans,
                           const float* __restrict__ W1,
                           const float* __restrict__ b1,
                           const float* __restrict__ W2,
                           float* __restrict__ logits) {
    const int lane = threadIdx.x;
    const int j = blockIdx.x * 32 + lane;
    const int brow = blockIdx.y * 8 + threadIdx.y;
    const int tid = threadIdx.y * 32 + threadIdx.x;

    __shared__ float sp[8][H_];   // 32 KB
    __shared__ float s_inv[8];

    if (tid < 8) {
        const int* row = spans + (blockIdx.y * 8 + tid) * (NSPANS_ * 2);
        int total = 0;
        #pragma unroll
        for (int m = 0; m < NSPANS_; m++) {
            int a = row[2 * m], e = row[2 * m + 1];
            if (a == 0 && e == 0) break;
            total += e - a;
        }
        s_inv[tid] = 1.0f / (float)total;
    }
    __syncthreads();

    // fill smem with pooled/total (float4)
    const float4* psrc = (const float4*)(pooled + blockIdx.y * 8 * H_);
    float4* pdst = (float4*)&sp[0][0];
    for (int k = tid; k < 8 * H4_; k += 256) {
        float4 v = psrc[k];
        const float inv = s_inv[k >> 8];
        v.x *= inv; v.y *= inv; v.z *= inv; v.w *= inv;
        pdst[k] = v;
    }
    __syncthreads();

    // fc1 dot: 4 independent accumulators break the FFMA chain
    const float* w = W1 + j;
    const float* p = sp[threadIdx.y];
    float c0 = 0.f, c1 = 0.f, c2 = 0.f, c3 = 0.f;
    #pragma unroll 4
    for (int i = 0; i < H_; i += 4) {
        c0 += p[i + 0] * w[(size_t)(i + 0) * H_];
        c1 += p[i + 1] * w[(size_t)(i + 1) * H_];
        c2 += p[i + 2] * w[(size_t)(i + 2) * H_];
        c3 += p[i + 3] * w[(size_t)(i + 3) * H_];
    }
    const float h = fmaxf((c0 + c1) + (c2 + c3) + b1[j], 0.f);

    // fc2 partial: broadcast each lane's h, lane c accumulates class c
    float accc = 0.f;
    const int jbase = blockIdx.x * 32;
    #pragma unroll
    for (int l = 0; l < 32; l++) {
        const float hv = __shfl_sync(0xffffffffu, h, l);
        if (lane < NCLS_)
            accc += hv * W2[(jbase + l) * NCLS_ + lane];
    }
    if (lane < NCLS_)
        atomicAdd(logits + brow * NCLS_ + lane, accc);
}

// ---------------------------------------------------------------------------
// Kernel 3: out = sigmoid(logits + b2). 800 elements.
// ---------------------------------------------------------------------------
__global__ void sigmoid_kernel(const float* __restrict__ logits,
                               const float* __restrict__ b2,
                               float* __restrict__ out) {
    const int idx = blockIdx.x * 256 + threadIdx.x;
    if (idx < B_ * NCLS_) {
        const float v = logits[idx] + b2[idx % NCLS_];
        out[idx] = 1.f / (1.f + __expf(-v));
    }
}

// ---------------------------------------------------------------------------
extern "C" void kernel_launch(void* const* d_in, const int* in_sizes, int n_in,
                              void* d_out, int out_size) {
    const float* all_emb = (const float*)d_in[0];
    const int*   spans   = (const int*)d_in[1];
    const float* W1      = (const float*)d_in[2];
    const float* b1      = (const float*)d_in[3];
    const float* W2      = (const float*)d_in[4];
    const float* b2      = (const float*)d_in[5];
    float* out = (float*)d_out;

    float* pooled;
    float* logits;
    cudaGetSymbolAddress((void**)&pooled, g_pooled);
    cudaGetSymbolAddress((void**)&logits, g_logits);

    zero_kernel<<<B_ * H_ / 256, 256>>>(pooled, logits);
    {
        dim3 grid(B_, NSPANS_, NCHUNK_);
        pool_kernel<<<grid, 256>>>(all_emb, spans, pooled);
    }
    {
        dim3 grid(H_ / 32, B_ / 8);
        dim3 block(32, 8);
        fc1_kernel<<<grid, block>>>(pooled, spans, W1, b1, W2, logits);
    }
    sigmoid_kernel<<<(B_ * NCLS_ + 255) / 256, 256>>>(logits, b2, out);
}